// round 2
// baseline (speedup 1.0000x reference)
#include <cuda_runtime.h>
#include <cuda_bf16.h>

#define BATCH 64
#define CHANS 3
#define HH 384
#define WW 384
#define HW (HH * WW)

__global__ __launch_bounds__(256)
void affine_kernel(const float* __restrict__ imgs,
                   const float* __restrict__ theta,
                   float* __restrict__ out) {
    // HW (147456) divisible by 256 -> no tail, all threads active (safe for __all_sync)
    const int pix = blockIdx.x * blockDim.x + threadIdx.x;
    const int b = blockIdx.y;
    const int row = pix / WW;
    const int col = pix - row * WW;

    const float* th = theta + b * 6;
    const float t00 = __ldg(th + 0);
    const float t01 = __ldg(th + 1);
    const float t02 = __ldg(th + 2);
    const float t10 = __ldg(th + 3);
    const float t11 = __ldg(th + 4);
    const float t12 = __ldg(th + 5);

    // ix = t00*(col-191.5) + t01*(row-191.5) + t02 + 191.5   (same for iy)
    const float xc = (float)col - 191.5f;
    const float yc = (float)row - 191.5f;
    const float ix = fmaf(t00, xc, fmaf(t01, yc, t02 + 191.5f));
    const float iy = fmaf(t10, xc, fmaf(t11, yc, t12 + 191.5f));

    const int x0 = __float2int_rd(ix);   // floor
    const int y0 = __float2int_rd(iy);
    const float wx1 = ix - (float)x0;
    const float wy1 = iy - (float)y0;
    const float wx0 = 1.0f - wx1;
    const float wy0 = 1.0f - wy1;

    const float w00 = wx0 * wy0;
    const float w10 = wx1 * wy0;
    const float w01 = wx0 * wy1;
    const float w11 = wx1 * wy1;

    const float* img = imgs + (size_t)b * (CHANS * HW);
    float* op = out + (size_t)b * (CHANS * HW) + pix;

    // interior: x0 in [0,382] and y0 in [0,382] -> all four taps in-bounds
    const bool interior = ((unsigned)x0 < (unsigned)(WW - 1)) &
                          ((unsigned)y0 < (unsigned)(HH - 1));

    if (__all_sync(0xFFFFFFFFu, interior)) {
        // One address computation; all 12 gathers are [base + imm].
        const float* p = img + y0 * WW + x0;
        float v00[CHANS], v10[CHANS], v01[CHANS], v11[CHANS];
#pragma unroll
        for (int c = 0; c < CHANS; c++) {
            const float* pc = p + c * HW;
            v00[c] = __ldg(pc);
            v10[c] = __ldg(pc + 1);
            v01[c] = __ldg(pc + WW);
            v11[c] = __ldg(pc + WW + 1);
        }
#pragma unroll
        for (int c = 0; c < CHANS; c++) {
            float acc = v00[c] * w00;
            acc = fmaf(v10[c], w10, acc);
            acc = fmaf(v01[c], w01, acc);
            acc = fmaf(v11[c], w11, acc);
            op[c * HW] = acc;
        }
    } else {
        // Generic path: clamp indices, fold validity into weights
        const int x1 = x0 + 1;
        const int y1 = y0 + 1;
        const float vx0 = ((unsigned)x0 < (unsigned)WW) ? 1.0f : 0.0f;
        const float vx1 = ((unsigned)x1 < (unsigned)WW) ? 1.0f : 0.0f;
        const float vy0 = ((unsigned)y0 < (unsigned)HH) ? 1.0f : 0.0f;
        const float vy1 = ((unsigned)y1 < (unsigned)HH) ? 1.0f : 0.0f;

        const float m00 = w00 * (vx0 * vy0);
        const float m10 = w10 * (vx1 * vy0);
        const float m01 = w01 * (vx0 * vy1);
        const float m11 = w11 * (vx1 * vy1);

        const int x0c = min(max(x0, 0), WW - 1);
        const int x1c = min(max(x1, 0), WW - 1);
        const int y0c = min(max(y0, 0), HH - 1);
        const int y1c = min(max(y1, 0), HH - 1);

        const int o00 = y0c * WW + x0c;
        const int o10 = y0c * WW + x1c;
        const int o01 = y1c * WW + x0c;
        const int o11 = y1c * WW + x1c;

        float v00[CHANS], v10[CHANS], v01[CHANS], v11[CHANS];
#pragma unroll
        for (int c = 0; c < CHANS; c++) {
            const float* pc = img + c * HW;
            v00[c] = __ldg(pc + o00);
            v10[c] = __ldg(pc + o10);
            v01[c] = __ldg(pc + o01);
            v11[c] = __ldg(pc + o11);
        }
#pragma unroll
        for (int c = 0; c < CHANS; c++) {
            float acc = v00[c] * m00;
            acc = fmaf(v10[c], m10, acc);
            acc = fmaf(v01[c], m01, acc);
            acc = fmaf(v11[c], m11, acc);
            op[c * HW] = acc;
        }
    }
}

extern "C" void kernel_launch(void* const* d_in, const int* in_sizes, int n_in,
                              void* d_out, int out_size) {
    const float* imgs  = (const float*)d_in[0];
    const float* theta = (const float*)d_in[1];
    float* out = (float*)d_out;

    dim3 block(256);
    dim3 grid(HW / 256, BATCH);  // 576 x 64
    affine_kernel<<<grid, block>>>(imgs, theta, out);
}